// round 7
// baseline (speedup 1.0000x reference)
#include <cuda_runtime.h>
#include <math.h>

#define THREADS 256
#define SUB 512           // points staged per sub-tile
#define GRID 592          // 4 * 148 SMs -> one wave at occupancy 4
#define NRANGE (GRID / 4) // point ranges (each range served by 4 corner-quarter blocks)

// Zero-initialized scratch; kernel self-restores zeros after each run
// (graph-replay deterministic, no init kernel needed).
__device__ unsigned int g_cmax[128];  // key = ~fenc(min d2) ; 0 == "empty"
__device__ unsigned int g_ctr;

// Robustly read a dimension that might arrive as int32/int64 or float32.
__device__ __forceinline__ float read_dim(const void* p) {
    int iv = *(const int*)p;                // little-endian: also low word of int64
    if (iv > 0 && iv < 1000000) return (float)iv;
    return *(const float*)p;
}

// Monotone total-order encoding of float -> unsigned (handles negatives).
__device__ __forceinline__ unsigned fenc(float f) {
    unsigned b = __float_as_uint(f);
    return (b & 0x80000000u) ? ~b : (b | 0x80000000u);
}
__device__ __forceinline__ float fdec(unsigned k) {
    return __uint_as_float((k & 0x80000000u) ? (k ^ 0x80000000u) : ~k);
}

__device__ __forceinline__ unsigned long long pack2(float lo, float hi) {
    unsigned long long d;
    asm("mov.b64 %0, {%1, %2};" : "=l"(d) : "f"(lo), "f"(hi));
    return d;
}
__device__ __forceinline__ void unpack2(unsigned long long d, float& lo, float& hi) {
    asm("mov.b64 {%0, %1}, %2;" : "=f"(lo), "=f"(hi) : "l"(d));
}

// One corner vs two points, replicating reference per-lane rounding:
//   t = rn(t1+s); p = rn(cx*u); d = rn(cy*v + p); d2 = rn(-2*d + t); m = min(m, d2)
__device__ __forceinline__ void corner_step(unsigned long long& m2,
                                            unsigned long long t12,
                                            unsigned long long cx2,
                                            unsigned long long cy2,
                                            unsigned long long u2,
                                            unsigned long long v2,
                                            unsigned long long s2,
                                            unsigned long long n2) {
    asm("{\n\t"
        ".reg .b64 t, p, d;\n\t"
        ".reg .f32 dlo, dhi, mlo, mhi;\n\t"
        "add.rn.f32x2 t, %1, %2;\n\t"
        "mul.rn.f32x2 p, %3, %4;\n\t"
        "fma.rn.f32x2 d, %5, %6, p;\n\t"
        "fma.rn.f32x2 d, %7, d, t;\n\t"
        "mov.b64 {dlo, dhi}, d;\n\t"
        "mov.b64 {mlo, mhi}, %0;\n\t"
        "min.f32 mlo, mlo, dlo;\n\t"
        "min.f32 mhi, mhi, dhi;\n\t"
        "mov.b64 %0, {mlo, mhi};\n\t"
        "}"
        : "+l"(m2)
        : "l"(t12), "l"(s2), "l"(cx2), "l"(u2), "l"(cy2), "l"(v2), "l"(n2));
}

__global__ void __launch_bounds__(THREADS, 4)
k_main(const float* __restrict__ P, const float* __restrict__ dtc,
       const float* __restrict__ cam, const float* __restrict__ theta,
       const float* __restrict__ va, const void* hp, const void* wp,
       int N, float* __restrict__ out) {
    __shared__ __align__(16) float su[SUB];
    __shared__ __align__(16) float sv[SUB];
    __shared__ __align__(16) float ss[SUB];
    __shared__ bool  isLast;
    __shared__ float red[128];

    const int tid  = threadIdx.x;
    const int warp = tid >> 5;
    const int lane = tid & 31;

    const int range = blockIdx.x >> 2;     // which point range
    const int cq    = blockIdx.x & 3;      // which 32-corner quarter

    // ---- Per-block fp32 camera setup (mirrors reference float32 pipeline) ----
    const float d2rf = 0.017453292519943295f;
    float rx = __fmul_rn(theta[0], d2rf);
    float ry = __fmul_rn(theta[1], d2rf);
    float rz = __fmul_rn(theta[2], d2rf);
    float cxa = cosf(rx), sxa = sinf(rx);
    float cya = cosf(ry), sya = sinf(ry);
    float cza = cosf(rz), sza = sinf(rz);
    // M = Ry @ Rx
    float M01 = __fmul_rn(sya, sxa), M02 = __fmul_rn(sya, cxa);
    float M11 = cxa,                 M12 = -sxa;
    float M20 = -sya, M21 = __fmul_rn(cya, sxa), M22 = __fmul_rn(cya, cxa);
    // R = Rz @ M  (row 2 of Rz is [0,0,1] -> row 2 of R = row 2 of M)
    const float R00 = __fmul_rn(cza, cya);
    const float R01 = __fsub_rn(__fmul_rn(cza, M01), __fmul_rn(sza, M11));
    const float R02 = __fsub_rn(__fmul_rn(cza, M02), __fmul_rn(sza, M12));
    const float R10 = __fmul_rn(sza, cya);
    const float R11 = __fadd_rn(__fmul_rn(sza, M01), __fmul_rn(cza, M11));
    const float R12 = __fadd_rn(__fmul_rn(sza, M02), __fmul_rn(cza, M12));
    const float R20 = M20, R21 = M21, R22 = M22;

    const float Hf = read_dim(hp), Wf = read_dim(wp);
    float vr = __fmul_rn(__fmul_rn(va[0], 0.5f), d2rf);
    const float f   = __fdiv_rn(-Hf, __fmul_rn(2.0f, tanf(vr)));
    const float kx0 = __fsub_rn(__fmul_rn(Wf, 0.5f), 0.5f);
    const float ky0 = __fsub_rn(__fmul_rn(Hf, 0.5f), 0.5f);
    const float camx = cam[0], camy = cam[1], camz = cam[2];

    // ---- This warp owns 4 corners as splatted f32x2 constants ----
    unsigned long long CX2[4], CY2[4], T12[4], M2[4];
    const int cbase = cq * 32 + warp * 4;
#pragma unroll
    for (int k = 0; k < 4; k++) {
        int c = cbase + k;
        float ccx = dtc[2 * c], ccy = dtc[2 * c + 1];
        CX2[k] = pack2(ccx, ccx);
        CY2[k] = pack2(ccy, ccy);
        float t1 = __fadd_rn(__fmul_rn(ccx, ccx), __fmul_rn(ccy, ccy));
        T12[k] = pack2(t1, t1);
        M2[k]  = pack2(3.4e38f, 3.4e38f);
    }
    const unsigned long long N2 = pack2(-2.0f, -2.0f);

    // Contiguous point range for this block quad.
    const int ppb   = (N + NRANGE - 1) / NRANGE;
    const int start = range * ppb;
    const int stop  = min(N, start + ppb);

    for (int base = start; base < stop; base += SUB) {
        const int nval = min(SUB, stop - base);

        // Project directly from gmem (coalesced; constants live in registers).
        for (int i = tid; i < SUB; i += THREADS) {
            float u = 0.0f, vf = 0.0f, s = 3.0e38f;
            if (i < nval) {
                const float* pp = P + 3 * (base + i);
                float px = pp[0], py = pp[1], pz = pp[2];
                float tx = __fadd_rn(px, -camx);
                float ty = __fadd_rn(py, -camy);
                float tz = __fadd_rn(pz, -camz);
                float x = __fmaf_rn(tz, R02, __fmaf_rn(ty, R01, __fmul_rn(tx, R00)));
                float y = __fmaf_rn(tz, R12, __fmaf_rn(ty, R11, __fmul_rn(tx, R10)));
                float z = __fmaf_rn(tz, R22, __fmaf_rn(ty, R21, __fmul_rn(tx, R20)));
                float xp = __fdiv_rn(x, z);
                float yp = __fdiv_rn(y, z);
                u  = __fmaf_rn(f, xp, kx0);
                float v = __fmaf_rn(f, yp, ky0);
                vf = __fadd_rn(Hf, -v);
                s  = __fadd_rn(__fmul_rn(u, u), __fmul_rn(vf, vf));
            }
            su[i] = u; sv[i] = vf; ss[i] = s;
        }
        __syncthreads();

        // Inner loop: 2 points per iteration as native f32x2 operands.
        const unsigned long long* u64 = (const unsigned long long*)su;
        const unsigned long long* v64 = (const unsigned long long*)sv;
        const unsigned long long* s64 = (const unsigned long long*)ss;
#pragma unroll 8
        for (int j = lane; j < SUB / 2; j += 32) {
            unsigned long long u2 = u64[j];
            unsigned long long v2 = v64[j];
            unsigned long long s2 = s64[j];
#pragma unroll
            for (int k = 0; k < 4; k++)
                corner_step(M2[k], T12[k], CX2[k], CY2[k], u2, v2, s2, N2);
        }
        __syncthreads();
    }

    // Merge packed halves (even/odd points), then warp butterfly reduce.
    float m[4];
#pragma unroll
    for (int k = 0; k < 4; k++) {
        float lo, hi;
        unpack2(M2[k], lo, hi);
        m[k] = fminf(lo, hi);
    }
#pragma unroll
    for (int off = 16; off >= 1; off >>= 1) {
#pragma unroll
        for (int k = 0; k < 4; k++)
            m[k] = fminf(m[k], __shfl_xor_sync(0xFFFFFFFFu, m[k], off));
    }
    if (lane == 0) {
#pragma unroll
        for (int k = 0; k < 4; k++)
            atomicMax(&g_cmax[cbase + k], ~fenc(m[k]));   // inverted key: init 0 is safe
    }

    // Last block: final deterministic sum + self-restore scratch to zero.
    __threadfence();
    __syncthreads();
    if (tid == 0) {
        unsigned old = atomicAdd(&g_ctr, 1u);
        isLast = (old == gridDim.x - 1u);
    }
    __syncthreads();
    if (isLast) {
        if (tid < 128) {
            red[tid] = fdec(~g_cmax[tid]);
            g_cmax[tid] = 0u;               // restore for next (graph) replay
        }
        if (tid == 0) g_ctr = 0u;
        __syncthreads();
        for (int off = 64; off > 0; off >>= 1) {
            if (tid < off) red[tid] += red[tid + off];
            __syncthreads();
        }
        if (tid == 0) out[0] = red[0];
    }
}

extern "C" void kernel_launch(void* const* d_in, const int* in_sizes, int n_in,
                              void* d_out, int out_size) {
    const float* PntCld = (const float*)d_in[0];
    const float* dtcCor = (const float*)d_in[1];
    const float* cam    = (const float*)d_in[2];
    const float* theta  = (const float*)d_in[3];
    const float* va     = (const float*)d_in[4];
    const void*  hp     = d_in[5];
    const void*  wp     = d_in[6];

    int N = in_sizes[0] / 3;

    k_main<<<GRID, THREADS>>>(PntCld, dtcCor, cam, theta, va, hp, wp,
                              N, (float*)d_out);
}